// round 5
// baseline (speedup 1.0000x reference)
#include <cuda_runtime.h>
#include <cstdint>

// GraphConv: out = segment_sum(x[src], dst, N) @ W2 + b2
// Pipeline: prep (zero cnt + idx-dtype detect) -> fill (bucketed counting sort)
//           -> gather (warp/node, fp32 exact) -> mma.sync tf32 3x GEMM (+bias)

constexpr int NN = 50000;
constexpr int FD = 128;
constexpr int NE = 600000;
constexpr int CAP = 64;
constexpr int OVF_CAP = 8192;

__device__ __align__(16) float g_agg[(size_t)NN * FD];
__device__ int g_cnt[NN];
__device__ int g_adj[(size_t)NN * CAP];
__device__ int g_ovf[OVF_CAP * 2];
__device__ int g_ovf_cnt;
__device__ int g_idx64;

// ---------------------------------------------------------------------------
__global__ void prep_kernel(const unsigned int* __restrict__ w) {
    int i = blockIdx.x * 256 + threadIdx.x;
    if (i < NN) g_cnt[i] = 0;
    if (blockIdx.x == 0) {
        if (threadIdx.x == 0) g_ovf_cnt = 0;
        __shared__ int found;
        if (threadIdx.x == 0) found = 0;
        __syncthreads();
        unsigned int v = 0;
        for (int j = threadIdx.x; j < 1024; j += 256) v |= w[2 * j + 1];
        if (v) atomicOr(&found, 1);
        __syncthreads();
        if (threadIdx.x == 0) g_idx64 = found ? 0 : 1;
    }
}

// ---------------------------------------------------------------------------
__global__ void fill_kernel(const void* __restrict__ ei_raw) {
    int e = blockIdx.x * blockDim.x + threadIdx.x;
    if (e >= NE) return;
    int src, dst;
    if (g_idx64) {
        const long long* ei = reinterpret_cast<const long long*>(ei_raw);
        src = (int)ei[e];
        dst = (int)ei[NE + e];
    } else {
        const int* ei = reinterpret_cast<const int*>(ei_raw);
        src = ei[e];
        dst = ei[NE + e];
    }
    int p = atomicAdd(&g_cnt[dst], 1);
    if (p < CAP) {
        g_adj[dst * CAP + p] = src;
    } else {
        int q = atomicAdd(&g_ovf_cnt, 1);
        if (q < OVF_CAP) { g_ovf[2 * q] = src; g_ovf[2 * q + 1] = dst; }
    }
}

// ---------------------------------------------------------------------------
// Gather: one warp per node; overflow (deg>CAP) handled in-warp (rare path).
// ---------------------------------------------------------------------------
__global__ __launch_bounds__(128) void gather_kernel(const float* __restrict__ x) {
    int n = blockIdx.x * 4 + (threadIdx.x >> 5);
    if (n >= NN) return;
    int lane = threadIdx.x & 31;

    int deg = g_cnt[n];
    const int* adjp = g_adj + (size_t)n * CAP;
    int a0 = adjp[lane];
    int a1 = adjp[lane + 32];

    float4 acc = make_float4(0.f, 0.f, 0.f, 0.f);

    if (deg > CAP) {
        int cnt = g_ovf_cnt;
        if (cnt > OVF_CAP) cnt = OVF_CAP;
        for (int q = 0; q < cnt; q++) {
            if (g_ovf[2 * q + 1] == n) {
                int s = g_ovf[2 * q];
                float4 v = *(reinterpret_cast<const float4*>(x + (size_t)s * FD) + lane);
                acc.x += v.x; acc.y += v.y; acc.z += v.z; acc.w += v.w;
            }
        }
        deg = CAP;
    }

    int j = 0;
    for (; j + 4 <= deg; j += 4) {
        int base = (j < 32) ? a0 : a1;
        int s0 = __shfl_sync(0xffffffffu, base, (j + 0) & 31);
        int s1 = __shfl_sync(0xffffffffu, base, (j + 1) & 31);
        int s2 = __shfl_sync(0xffffffffu, base, (j + 2) & 31);
        int s3 = __shfl_sync(0xffffffffu, base, (j + 3) & 31);
        float4 v0 = *(reinterpret_cast<const float4*>(x + (size_t)s0 * FD) + lane);
        float4 v1 = *(reinterpret_cast<const float4*>(x + (size_t)s1 * FD) + lane);
        float4 v2 = *(reinterpret_cast<const float4*>(x + (size_t)s2 * FD) + lane);
        float4 v3 = *(reinterpret_cast<const float4*>(x + (size_t)s3 * FD) + lane);
        acc.x += v0.x + v1.x + v2.x + v3.x;
        acc.y += v0.y + v1.y + v2.y + v3.y;
        acc.z += v0.z + v1.z + v2.z + v3.z;
        acc.w += v0.w + v1.w + v2.w + v3.w;
    }
    for (; j < deg; j++) {
        int base = (j < 32) ? a0 : a1;
        int s = __shfl_sync(0xffffffffu, base, j & 31);
        float4 v = *(reinterpret_cast<const float4*>(x + (size_t)s * FD) + lane);
        acc.x += v.x; acc.y += v.y; acc.z += v.z; acc.w += v.w;
    }
    *(reinterpret_cast<float4*>(g_agg + (size_t)n * FD) + lane) = acc;
}

// ---------------------------------------------------------------------------
// 3xTF32 mma.sync GEMM: out[128 rows] = agg @ W2 + b2.
// CTA: 256 threads = 8 warps; warp w owns rows [w*16, w*16+16) x all 128 cols.
// A,B staged fp32 in smem ([128][132] pad); hi/lo tf32 split at fragment load.
// ---------------------------------------------------------------------------
constexpr int LDA = 132;
constexpr int GS_A = 0;
constexpr int GS_B = FD * LDA;                      // floats
constexpr int GS_BIAS = 2 * FD * LDA;
constexpr int GEMM_SMEM = (2 * FD * LDA + FD) * 4;  // 135,680 B

__device__ __forceinline__ uint32_t f2tf32(float f) {
    uint32_t r;
    asm("cvt.rna.tf32.f32 %0, %1;" : "=r"(r) : "f"(f));
    return r;
}
__device__ __forceinline__ void split_tf32(float v, uint32_t& hi, uint32_t& lo) {
    hi = f2tf32(v);
    lo = f2tf32(v - __uint_as_float(hi));
}
__device__ __forceinline__ void mma8(float* c, uint32_t a0, uint32_t a1, uint32_t a2,
                                     uint32_t a3, uint32_t b0, uint32_t b1) {
    asm volatile(
        "mma.sync.aligned.m16n8k8.row.col.f32.tf32.tf32.f32 "
        "{%0,%1,%2,%3}, {%4,%5,%6,%7}, {%8,%9}, {%0,%1,%2,%3};"
        : "+f"(c[0]), "+f"(c[1]), "+f"(c[2]), "+f"(c[3])
        : "r"(a0), "r"(a1), "r"(a2), "r"(a3), "r"(b0), "r"(b1));
}

__global__ __launch_bounds__(256, 1) void gemm_kernel(const float* __restrict__ W2,
                                                      const float* __restrict__ b2,
                                                      float* __restrict__ out) {
    extern __shared__ float smem[];
    float* As = smem + GS_A;
    float* Bs = smem + GS_B;
    float* bias = smem + GS_BIAS;

    int tid = threadIdx.x;
    int row0 = blockIdx.x * 128;

    // Stage A (agg rows) and B (W2) in fp32, float4-coalesced.
    {
        const float4* ag = reinterpret_cast<const float4*>(g_agg);
        const float4* bg = reinterpret_cast<const float4*>(W2);
#pragma unroll
        for (int it = 0; it < 16; it++) {
            int idx = tid + it * 256;            // 0..4095
            int r = idx >> 5, c = idx & 31;
            float4 av = make_float4(0.f, 0.f, 0.f, 0.f);
            if (row0 + r < NN) av = ag[(size_t)(row0 + r) * 32 + c];
            *reinterpret_cast<float4*>(As + r * LDA + c * 4) = av;
            *reinterpret_cast<float4*>(Bs + r * LDA + c * 4) = bg[(size_t)r * 32 + c];
        }
    }
    if (tid < FD) bias[tid] = b2[tid];
    __syncthreads();

    int wid = tid >> 5;
    int lane = tid & 31;
    int g = lane >> 2;      // 0..7
    int t = lane & 3;       // 0..3
    int r0 = wid * 16;

    float acc[16][4];
#pragma unroll
    for (int i = 0; i < 16; i++)
#pragma unroll
        for (int j = 0; j < 4; j++) acc[i][j] = 0.f;

#pragma unroll
    for (int ks = 0; ks < 16; ks++) {
        int k0 = ks * 8;
        const float* Ap = As + (r0 + g) * LDA + k0 + t;
        uint32_t ah[4], al[4];
        split_tf32(Ap[0], ah[0], al[0]);
        split_tf32(Ap[8 * LDA], ah[1], al[1]);
        split_tf32(Ap[4], ah[2], al[2]);
        split_tf32(Ap[8 * LDA + 4], ah[3], al[3]);

        const float* Bp0 = Bs + (k0 + t) * LDA + g;
        const float* Bp1 = Bp0 + 4 * LDA;
#pragma unroll
        for (int nt = 0; nt < 16; nt++) {
            uint32_t bh0, bl0, bh1, bl1;
            split_tf32(Bp0[nt * 8], bh0, bl0);
            split_tf32(Bp1[nt * 8], bh1, bl1);
            mma8(acc[nt], ah[0], ah[1], ah[2], ah[3], bh0, bh1);
            mma8(acc[nt], al[0], al[1], al[2], al[3], bh0, bh1);
            mma8(acc[nt], ah[0], ah[1], ah[2], ah[3], bl0, bl1);
        }
    }

    // Epilogue: c0/c1 at (row, 2t), c2/c3 at (row+8, 2t) within each n-tile.
    int rA = row0 + r0 + g;
    int rB = rA + 8;
#pragma unroll
    for (int nt = 0; nt < 16; nt++) {
        int col = nt * 8 + 2 * t;
        float bx = bias[col], by = bias[col + 1];
        if (rA < NN) {
            float2 v = make_float2(acc[nt][0] + bx, acc[nt][1] + by);
            *reinterpret_cast<float2*>(out + (size_t)rA * FD + col) = v;
        }
        if (rB < NN) {
            float2 v = make_float2(acc[nt][2] + bx, acc[nt][3] + by);
            *reinterpret_cast<float2*>(out + (size_t)rB * FD + col) = v;
        }
    }
}

// ---------------------------------------------------------------------------
extern "C" void kernel_launch(void* const* d_in, const int* in_sizes, int n_in,
                              void* d_out, int out_size) {
    const float* x  = (const float*)d_in[0];
    const void*  ei = d_in[1];
    // d_in[2]=edge_weight, d_in[3]=W1, d_in[4]=b1 : dead in reference
    const float* W2 = (const float*)d_in[5];
    const float* b2 = (const float*)d_in[6];
    float* out = (float*)d_out;

    cudaFuncSetAttribute(gemm_kernel, cudaFuncAttributeMaxDynamicSharedMemorySize, GEMM_SMEM);

    prep_kernel<<<(NN + 255) / 256, 256>>>((const unsigned int*)ei);
    fill_kernel<<<(NE + 255) / 256, 256>>>(ei);
    gather_kernel<<<(NN + 3) / 4, 128>>>(x);
    gemm_kernel<<<(NN + 127) / 128, 256, GEMM_SMEM>>>(W2, b2, out);
}

// round 6
// speedup vs baseline: 1.7256x; 1.7256x over previous
#include <cuda_runtime.h>
#include <cstdint>

// GraphConv: out = segment_sum(x[src], dst, N) @ W2 + b2
// Pipeline: prep (zero cnt + detect + W2 bf16-split fragment table) ->
//           fill (bucketed counting sort) -> gather (warp/node, writes bf16 hi/lo planes)
//           -> 3xBF16 mma.sync GEMM (+bias)

constexpr int NN = 50000;
constexpr int FD = 128;
constexpr int NE = 600000;
constexpr int CAP = 64;
constexpr int OVF_CAP = 8192;

__device__ int g_cnt[NN];
__device__ int g_adj[(size_t)NN * CAP];
__device__ int g_ovf[OVF_CAP * 2];
__device__ int g_ovf_cnt;
__device__ int g_idx64;
__device__ __align__(16) uint32_t g_Ah[(size_t)NN * 64];   // bf16x2 hi plane
__device__ __align__(16) uint32_t g_Al[(size_t)NN * 64];   // bf16x2 lo plane
__device__ __align__(16) uint4 g_Bfrag[8 * 16 * 32];       // W2 frags: {bh0,bh1,bl0,bl1}

// ---------------------------------------------------------------------------
__device__ __forceinline__ uint32_t pack_bf16(float lo, float hi) {
    uint32_t r;
    asm("cvt.rn.bf16x2.f32 %0, %1, %2;" : "=r"(r) : "f"(hi), "f"(lo));
    return r;
}
__device__ __forceinline__ float bf_lo(uint32_t u) { return __uint_as_float(u << 16); }
__device__ __forceinline__ float bf_hi(uint32_t u) { return __uint_as_float(u & 0xFFFF0000u); }

// split pair (f0,f1) -> hi word + lo word
__device__ __forceinline__ void split2(float f0, float f1, uint32_t& h, uint32_t& l) {
    h = pack_bf16(f0, f1);
    l = pack_bf16(f0 - bf_lo(h), f1 - bf_hi(h));
}

// ---------------------------------------------------------------------------
// Blocks [0,ZB): zero counters (+ dtype detect in block 0).
// Blocks [ZB, ZB+16): build g_Bfrag from W2.
// ---------------------------------------------------------------------------
constexpr int ZB = (NN + 255) / 256;

__global__ void prep_kernel(const unsigned int* __restrict__ w,
                            const float* __restrict__ W2) {
    if (blockIdx.x < ZB) {
        int i = blockIdx.x * 256 + threadIdx.x;
        if (i < NN) g_cnt[i] = 0;
        if (blockIdx.x == 0) {
            if (threadIdx.x == 0) g_ovf_cnt = 0;
            __shared__ int found;
            if (threadIdx.x == 0) found = 0;
            __syncthreads();
            unsigned int v = 0;
            for (int j = threadIdx.x; j < 1024; j += 256) v |= w[2 * j + 1];
            if (v) atomicOr(&found, 1);
            __syncthreads();
            if (threadIdx.x == 0) g_idx64 = found ? 0 : 1;
        }
    } else {
        int i = (blockIdx.x - ZB) * 256 + threadIdx.x;  // 0..4095
        int lane = i & 31, nt = (i >> 5) & 15, ks = i >> 9;
        int g = lane >> 2, t = lane & 3;
        int n = nt * 8 + g, k0 = ks * 16;
        float v00 = W2[(k0 + 2 * t) * FD + n];
        float v01 = W2[(k0 + 2 * t + 1) * FD + n];
        float v10 = W2[(k0 + 2 * t + 8) * FD + n];
        float v11 = W2[(k0 + 2 * t + 9) * FD + n];
        uint4 f;
        split2(v00, v01, f.x, f.z);
        split2(v10, v11, f.y, f.w);
        g_Bfrag[i] = f;
    }
}

// ---------------------------------------------------------------------------
__global__ void fill_kernel(const void* __restrict__ ei_raw) {
    int e = blockIdx.x * blockDim.x + threadIdx.x;
    if (e >= NE) return;
    int src, dst;
    if (g_idx64) {
        const long long* ei = reinterpret_cast<const long long*>(ei_raw);
        src = (int)ei[e];
        dst = (int)ei[NE + e];
    } else {
        const int* ei = reinterpret_cast<const int*>(ei_raw);
        src = ei[e];
        dst = ei[NE + e];
    }
    int p = atomicAdd(&g_cnt[dst], 1);
    if (p < CAP) {
        g_adj[dst * CAP + p] = src;
    } else {
        int q = atomicAdd(&g_ovf_cnt, 1);
        if (q < OVF_CAP) { g_ovf[2 * q] = src; g_ovf[2 * q + 1] = dst; }
    }
}

// ---------------------------------------------------------------------------
// Gather: warp/node; writes bf16 hi/lo split planes (exact fp32 accumulate).
// ---------------------------------------------------------------------------
__global__ __launch_bounds__(128) void gather_kernel(const float* __restrict__ x) {
    int n = blockIdx.x * 4 + (threadIdx.x >> 5);
    if (n >= NN) return;
    int lane = threadIdx.x & 31;

    int deg = g_cnt[n];
    const int* adjp = g_adj + (size_t)n * CAP;
    int a0 = adjp[lane];
    int a1 = adjp[lane + 32];

    float4 acc = make_float4(0.f, 0.f, 0.f, 0.f);

    if (deg > CAP) {
        int cnt = g_ovf_cnt;
        if (cnt > OVF_CAP) cnt = OVF_CAP;
        for (int q = 0; q < cnt; q++) {
            if (g_ovf[2 * q + 1] == n) {
                int s = g_ovf[2 * q];
                float4 v = *(reinterpret_cast<const float4*>(x + (size_t)s * FD) + lane);
                acc.x += v.x; acc.y += v.y; acc.z += v.z; acc.w += v.w;
            }
        }
        deg = CAP;
    }

    int j = 0;
    for (; j + 4 <= deg; j += 4) {
        int base = (j < 32) ? a0 : a1;
        int s0 = __shfl_sync(0xffffffffu, base, (j + 0) & 31);
        int s1 = __shfl_sync(0xffffffffu, base, (j + 1) & 31);
        int s2 = __shfl_sync(0xffffffffu, base, (j + 2) & 31);
        int s3 = __shfl_sync(0xffffffffu, base, (j + 3) & 31);
        float4 v0 = *(reinterpret_cast<const float4*>(x + (size_t)s0 * FD) + lane);
        float4 v1 = *(reinterpret_cast<const float4*>(x + (size_t)s1 * FD) + lane);
        float4 v2 = *(reinterpret_cast<const float4*>(x + (size_t)s2 * FD) + lane);
        float4 v3 = *(reinterpret_cast<const float4*>(x + (size_t)s3 * FD) + lane);
        acc.x += v0.x + v1.x + v2.x + v3.x;
        acc.y += v0.y + v1.y + v2.y + v3.y;
        acc.z += v0.z + v1.z + v2.z + v3.z;
        acc.w += v0.w + v1.w + v2.w + v3.w;
    }
    for (; j < deg; j++) {
        int base = (j < 32) ? a0 : a1;
        int s = __shfl_sync(0xffffffffu, base, j & 31);
        float4 v = *(reinterpret_cast<const float4*>(x + (size_t)s * FD) + lane);
        acc.x += v.x; acc.y += v.y; acc.z += v.z; acc.w += v.w;
    }

    uint32_t h0, l0, h1, l1;
    split2(acc.x, acc.y, h0, l0);
    split2(acc.z, acc.w, h1, l1);
    uint2 hv = make_uint2(h0, h1), lv = make_uint2(l0, l1);
    *reinterpret_cast<uint2*>(g_Ah + (size_t)n * 64 + lane * 2) = hv;
    *reinterpret_cast<uint2*>(g_Al + (size_t)n * 64 + lane * 2) = lv;
}

// ---------------------------------------------------------------------------
// 3xBF16 GEMM: out[128-row tile] = agg @ W2 + b2.
// 256 thr = 8 warps; warp w: rows [w*16, w*16+16) x 128 cols.
// smem: Ah [0,34816) Al [34816,69632) rows of 272B; Bfrag [69632,135168); bias.
// ---------------------------------------------------------------------------
constexpr int LDAB = 272;
constexpr int SM_AL = 128 * LDAB;            // 34816
constexpr int SM_BF = 2 * 128 * LDAB;        // 69632
constexpr int SM_BIAS = SM_BF + 65536;       // 135168
constexpr int GEMM_SMEM = SM_BIAS + 512;     // 135680

__device__ __forceinline__ void mma16(float* c, uint32_t a0, uint32_t a1, uint32_t a2,
                                      uint32_t a3, uint32_t b0, uint32_t b1) {
    asm volatile(
        "mma.sync.aligned.m16n8k16.row.col.f32.bf16.bf16.f32 "
        "{%0,%1,%2,%3}, {%4,%5,%6,%7}, {%8,%9}, {%0,%1,%2,%3};"
        : "+f"(c[0]), "+f"(c[1]), "+f"(c[2]), "+f"(c[3])
        : "r"(a0), "r"(a1), "r"(a2), "r"(a3), "r"(b0), "r"(b1));
}

__global__ __launch_bounds__(256, 1) void gemm_kernel(const float* __restrict__ b2,
                                                      float* __restrict__ out) {
    extern __shared__ char smem[];
    int tid = threadIdx.x;
    int row0 = blockIdx.x * 128;

    // Stage A hi/lo planes (16 uint4 per 128-col row)
    {
        const uint4* ahg = reinterpret_cast<const uint4*>(g_Ah);
        const uint4* alg = reinterpret_cast<const uint4*>(g_Al);
#pragma unroll
        for (int it = 0; it < 8; it++) {
            int idx = tid + it * 256;            // 0..2047
            int r = idx >> 4, cg = idx & 15;
            uint4 zv = make_uint4(0, 0, 0, 0);
            uint4 hv = zv, lv = zv;
            if (row0 + r < NN) {
                hv = ahg[(size_t)(row0 + r) * 16 + cg];
                lv = alg[(size_t)(row0 + r) * 16 + cg];
            }
            *reinterpret_cast<uint4*>(smem + r * LDAB + cg * 16) = hv;
            *reinterpret_cast<uint4*>(smem + SM_AL + r * LDAB + cg * 16) = lv;
        }
    }
    // Stage B fragment table (64KB)
    {
        uint4* bs = reinterpret_cast<uint4*>(smem + SM_BF);
#pragma unroll
        for (int it = 0; it < 16; it++) {
            int idx = tid + it * 256;
            bs[idx] = g_Bfrag[idx];
        }
    }
    if (tid < FD) reinterpret_cast<float*>(smem + SM_BIAS)[tid] = b2[tid];
    __syncthreads();

    int wid = tid >> 5;
    int lane = tid & 31;
    int g = lane >> 2;
    int t = lane & 3;

    const char* Ah_base = smem + (wid * 16 + g) * LDAB + 4 * t;
    const char* Al_base = Ah_base + SM_AL;

    float acc[16][4];
#pragma unroll
    for (int i = 0; i < 16; i++)
#pragma unroll
        for (int j = 0; j < 4; j++) acc[i][j] = 0.f;

#pragma unroll
    for (int ks = 0; ks < 8; ks++) {
        int ko = ks * 32;   // 16 cols bf16 = 32B
        uint32_t ah0 = *reinterpret_cast<const uint32_t*>(Ah_base + ko);
        uint32_t ah1 = *reinterpret_cast<const uint32_t*>(Ah_base + ko + 8 * LDAB);
        uint32_t ah2 = *reinterpret_cast<const uint32_t*>(Ah_base + ko + 16);
        uint32_t ah3 = *reinterpret_cast<const uint32_t*>(Ah_base + ko + 8 * LDAB + 16);
        uint32_t al0 = *reinterpret_cast<const uint32_t*>(Al_base + ko);
        uint32_t al1 = *reinterpret_cast<const uint32_t*>(Al_base + ko + 8 * LDAB);
        uint32_t al2 = *reinterpret_cast<const uint32_t*>(Al_base + ko + 16);
        uint32_t al3 = *reinterpret_cast<const uint32_t*>(Al_base + ko + 8 * LDAB + 16);

        const uint4* Bf = reinterpret_cast<const uint4*>(smem + SM_BF) + ks * 16 * 32 + lane;
#pragma unroll
        for (int nt = 0; nt < 16; nt++) {
            uint4 b = Bf[nt * 32];
            mma16(acc[nt], ah0, ah1, ah2, ah3, b.x, b.y);   // ah*bh
            mma16(acc[nt], al0, al1, al2, al3, b.x, b.y);   // al*bh
            mma16(acc[nt], ah0, ah1, ah2, ah3, b.z, b.w);   // ah*bl
        }
    }

    const float* bias = reinterpret_cast<const float*>(smem + SM_BIAS);
    int rA = row0 + wid * 16 + g;
    int rB = rA + 8;
#pragma unroll
    for (int nt = 0; nt < 16; nt++) {
        int col = nt * 8 + 2 * t;
        float bx = bias[col], by = bias[col + 1];
        if (rA < NN) {
            float2 v = make_float2(acc[nt][0] + bx, acc[nt][1] + by);
            *reinterpret_cast<float2*>(out + (size_t)rA * FD + col) = v;
        }
        if (rB < NN) {
            float2 v = make_float2(acc[nt][2] + bx, acc[nt][3] + by);
            *reinterpret_cast<float2*>(out + (size_t)rB * FD + col) = v;
        }
    }
}

// ---------------------------------------------------------------------------
extern "C" void kernel_launch(void* const* d_in, const int* in_sizes, int n_in,
                              void* d_out, int out_size) {
    const float* x  = (const float*)d_in[0];
    const void*  ei = d_in[1];
    // d_in[2]=edge_weight, d_in[3]=W1, d_in[4]=b1 : dead in reference
    const float* W2 = (const float*)d_in[5];
    const float* b2 = (const float*)d_in[6];
    float* out = (float*)d_out;

    cudaFuncSetAttribute(gemm_kernel, cudaFuncAttributeMaxDynamicSharedMemorySize, GEMM_SMEM);

    prep_kernel<<<ZB + 16, 256>>>((const unsigned int*)ei, W2);
    fill_kernel<<<(NE + 255) / 256, 256>>>(ei);
    gather_kernel<<<(NN + 3) / 4, 128>>>(x);
    gemm_kernel<<<(NN + 127) / 128, 256, GEMM_SMEM>>>(b2, out);
}